// round 16
// baseline (speedup 1.0000x reference)
#include <cuda_runtime.h>
#include <cuda_fp16.h>
#include <math.h>
#include <cstdint>

// ---------------------------------------------------------------------------
// SimplifiedIFEBranch — R16: R7 pipeline, but fc1 via mma.sync m16n8k16
// (HMMA, supported on plain sm_103) with fp16 hi/lo split for fp32 accuracy.
// Operands staged fragment-contiguous in smem. fc2/fc3/hist = R7-exact.
// ---------------------------------------------------------------------------

#define NCTA 128

// dynamic smem byte layout
#define A_HI_B 0         // A (W1 tile) hi frags: 24576 half = 49152 B
#define A_LO_B 49152
#define B_HI_B 98304     // B (hist) hi frags: 24576 half = 49152 B (bins in ph0)
#define B_LO_B 147456
#define W2_B   196608    // fc2 W tile 16x256 f32 = 16384 B
#define W3_B   212992    // fc3 W tile 2x512 f32  =  4096 B
#define SMEM_BYTES 217088

__device__ __forceinline__ float c_LO() { return (float)(-3.2 - (6.4 / 256.0) / 2.0); }
__device__ __forceinline__ float c_HI() { return (float)( 3.2 - (6.4 / 256.0) / 2.0); }
__device__ __forceinline__ float c_BW() {
    return (float)(((3.2 - (6.4 / 256.0) / 2.0) - (-3.2 - (6.4 / 256.0) / 2.0)) / 32.0);
}

// Scratch (__device__ globals)
__device__ float g_histP[3072 * 32];   // pair-packed: [(k/2)][b][2]
__device__ float g_x1T[1024 * 32];     // [n][b], bias-preinit accum
__device__ float g_x2T[512 * 32];
__device__ unsigned int g_bar_count = 0;
__device__ unsigned int g_bar_gen   = 0;

typedef unsigned long long ull;

// ---- packed f32x2 helpers (fc2/fc3 SIMT path) --------------------------------
__device__ __forceinline__ ull pack2(float x, float y) {
    ull r; asm("mov.b64 %0, {%1, %2};" : "=l"(r) : "f"(x), "f"(y)); return r;
}
__device__ __forceinline__ void ffma2(ull& d, ull a, ull b) {
    asm("fma.rn.f32x2 %0, %1, %2, %0;" : "+l"(d) : "l"(a), "l"(b));
}
__device__ __forceinline__ float unpack_sum(ull p) {
    float lo, hi; asm("mov.b64 {%0, %1}, %2;" : "=f"(lo), "=f"(hi) : "l"(p));
    return lo + hi;
}

// ---- HMMA m16n8k16 f16 -> f32 ---------------------------------------------------
__device__ __forceinline__ void mma16816(float& d0, float& d1, float& d2, float& d3,
                                         uint4 a, uint2 b) {
    asm volatile(
        "mma.sync.aligned.m16n8k16.row.col.f32.f16.f16.f32 "
        "{%0,%1,%2,%3}, {%4,%5,%6,%7}, {%8,%9}, {%0,%1,%2,%3};"
        : "+f"(d0), "+f"(d1), "+f"(d2), "+f"(d3)
        : "r"(a.x), "r"(a.y), "r"(a.z), "r"(a.w), "r"(b.x), "r"(b.y));
}

// ---- software grid barrier (R7) ----------------------------------------------
__device__ __forceinline__ void grid_barrier() {
    __syncthreads();
    if (threadIdx.x == 0) {
        unsigned gen = *(volatile unsigned*)&g_bar_gen;
        __threadfence();
        unsigned old = atomicAdd(&g_bar_count, 1u);
        if (old == NCTA - 1) {
            g_bar_count = 0;
            __threadfence();
            atomicAdd(&g_bar_gen, 1u);
        } else {
            while (*(volatile unsigned*)&g_bar_gen == gen) { __nanosleep(32); }
        }
        __threadfence();
    }
    __syncthreads();
}

// ---- histogram helper -----------------------------------------------------------
__device__ __forceinline__ void hist_add(float* h, float Iu, float Iv, float w) {
    const float LO = c_LO(), HI = c_HI(), BW = c_BW();
    if (Iu >= LO && Iu <= HI && Iv >= LO && Iv <= HI) {
        int iu = (int)floorf((Iu - LO) / BW);
        int iv = (int)floorf((Iv - LO) / BW);
        iu = min(max(iu, 0), 31);
        iv = min(max(iv, 0), 31);
        atomicAdd(&h[iu * 32 + iv], w);
    }
}

// ---- coalesced W tile stage (fc2/fc3) ---------------------------------------------
template <int ROWS, int COLS>
__device__ __forceinline__ void stage_tile(float* dst, const float* src, int ld) {
    constexpr int F4 = ROWS * COLS / 4;
    constexpr int RF = COLS / 4;
    #pragma unroll
    for (int f = threadIdx.x; f < F4; f += 512) {
        const int row = f / RF, col = f - row * RF;
        reinterpret_cast<float4*>(dst)[f] = __ldcg(
            reinterpret_cast<const float4*>(src + (size_t)row * ld + col * 4));
    }
}

// ---- FC SIMT compute (R7-exact) ------------------------------------------------------
template <int KS, int NROWS, int NT, int NG, int KG, int HALVES,
          bool RELU_IN, bool PACKED_A, bool ATOMIC_OUT>
__device__ __forceinline__ void fc_compute(const float* __restrict__ AT,
                                           const float* wtile,
                                           const float* __restrict__ bias,
                                           float* __restrict__ dest, int ldo,
                                           float* scratch, int n0, int K0) {
    constexpr int CH = KS / KG;
    constexpr int NK = CH / HALVES;
    const int tid  = threadIdx.x;
    const int lane = tid & 31;
    const int w    = tid >> 5;
    const int kg   = w / NG;
    const int ng   = w % NG;

    ull acc2[NT];
    #pragma unroll
    for (int t = 0; t < NT; ++t) acc2[t] = 0ull;

    const int kbase = K0 + kg * CH;
    const float* wrow0 = wtile + (size_t)(ng * NT) * KS + kg * CH;

    #pragma unroll
    for (int h = 0; h < HALVES; ++h) {
        const int kh = kbase + h * NK;
        ull ap[NK / 2];
        if (PACKED_A) {
            const ull* src = reinterpret_cast<const ull*>(AT) + (size_t)(kh >> 1) * 32 + lane;
            #pragma unroll
            for (int j = 0; j < NK / 2; ++j) ap[j] = __ldcg(src + (size_t)j * 32);
        } else {
            #pragma unroll
            for (int j = 0; j < NK / 2; ++j) {
                float a0 = __ldcg(AT + (size_t)(kh + 2 * j) * 32 + lane);
                float a1 = __ldcg(AT + (size_t)(kh + 2 * j + 1) * 32 + lane);
                if (RELU_IN) { a0 = fmaxf(a0, 0.f); a1 = fmaxf(a1, 0.f); }
                ap[j] = pack2(a0, a1);
            }
        }
        #pragma unroll
        for (int j2 = 0; j2 < NK / 4; ++j2) {
            #pragma unroll
            for (int t = 0; t < NT; ++t) {
                ulonglong2 wv = *reinterpret_cast<const ulonglong2*>(
                    wrow0 + (size_t)t * KS + h * NK + 4 * j2);
                ffma2(acc2[t], wv.x, ap[2 * j2]);
                ffma2(acc2[t], wv.y, ap[2 * j2 + 1]);
            }
        }
    }
    __syncthreads();

    #pragma unroll
    for (int t = 0; t < NT; ++t)
        scratch[(w * NT + t) * 32 + lane] = unpack_sum(acc2[t]);
    __syncthreads();

    for (int n = w; n < NROWS; n += 16) {
        const int nng = n / NT, tt = n % NT;
        float s = 0.0f;
        #pragma unroll
        for (int kk = 0; kk < KG; ++kk)
            s += scratch[((kk * NG + nng) * NT + tt) * 32 + lane];
        if (ATOMIC_OUT) {
            atomicAdd(&dest[(size_t)(n0 + n) * 32 + lane], s);
        } else {
            s += __ldcg(bias + n0 + n);
            s = fmaxf(s, 0.0f);
            dest[(size_t)lane * ldo + n0 + n] = s;
        }
    }
    __syncthreads();
}

// ---- fp16 hi/lo split of a float2 -> two packed half2 words ------------------------
__device__ __forceinline__ void split_h2(float2 v, unsigned& hi, unsigned& lo) {
    __half2 h2 = __floats2half2_rn(v.x, v.y);
    float2 hf = __half22float2(h2);
    __half2 l2 = __floats2half2_rn(v.x - hf.x, v.y - hf.y);
    hi = *reinterpret_cast<unsigned*>(&h2);
    lo = *reinterpret_cast<unsigned*>(&l2);
}

// ---- the one kernel ------------------------------------------------------------------
__global__ __launch_bounds__(512, 1) void fused_kernel(
    const float* __restrict__ img,
    const float* __restrict__ W1, const float* __restrict__ b1,
    const float* __restrict__ W2, const float* __restrict__ b2,
    const float* __restrict__ W3, const float* __restrict__ b3,
    float* __restrict__ out,
    float* __restrict__ histP, float* __restrict__ x1T, float* __restrict__ x2T) {

    extern __shared__ float buf[];
    char* bufb = reinterpret_cast<char*>(buf);
    __shared__ float ssum[3];

    const int cta  = blockIdx.x;
    const int tid  = threadIdx.x;
    const int lane = tid & 31;
    const int wid  = tid >> 5;

    // ---- hist pixel loads first (latency overlaps staging) ---------------------
    float r0 = 0, g0 = 0, l0 = 0, r1 = 0, g1 = 0, l1 = 0;
    if (cta < 32) {
        const float* base = img + (size_t)cta * 3 * 262144;
        const int p0 = tid, p1 = tid + 512;
        const int off0 = ((p0 >> 5) * 16) * 512 + ((p0 & 31) * 16);
        const int off1 = ((p1 >> 5) * 16) * 512 + ((p1 & 31) * 16);
        r0 = __ldcg(base + off0);
        g0 = __ldcg(base + 262144 + off0);
        l0 = __ldcg(base + 524288 + off0);
        r1 = __ldcg(base + off1);
        g1 = __ldcg(base + 262144 + off1);
        l1 = __ldcg(base + 524288 + off1);
    }

    // ---- Phase 0a: stage fc1 A (W1 tile 32n x 768k) as fp16 hi/lo FRAGMENTS ----
    // dest layout: u32[((mtile*48 + ks)*32 + t)*4 + u]
    //   mtile=n/16, r=n%16, ks=kpair/8, j=kpair%8, t=(r&7)*4+(j&3), u=(r>>3)+(j>>2)*2
    {
        const float* w1s = W1 + (size_t)((cta & 31) * 32) * 3072 + (cta >> 5) * 768;
        unsigned* ah = reinterpret_cast<unsigned*>(bufb + A_HI_B);
        unsigned* al = reinterpret_cast<unsigned*>(bufb + A_LO_B);
        #pragma unroll 4
        for (int idx = tid; idx < 12288; idx += 512) {
            const int n = idx / 384, jp = idx - n * 384;
            float2 v = __ldcg(reinterpret_cast<const float2*>(
                w1s + (size_t)n * 3072 + jp * 2));
            unsigned hi, lo;
            split_h2(v, hi, lo);
            const int mtile = n >> 4, r = n & 15, ks = jp >> 3, j = jp & 7;
            const int t = (r & 7) * 4 + (j & 3);
            const int u = (r >> 3) + (j >> 2) * 2;
            const int a32 = ((mtile * 48 + ks) * 32 + t) * 4 + u;
            ah[a32] = hi;
            al[a32] = lo;
        }
    }

    // ---- Phase 0b: fc2/fc3 W tiles + bias pre-init -------------------------------
    stage_tile<16, 256>(reinterpret_cast<float*>(bufb + W2_B),
                        W2 + (size_t)((cta & 31) * 16) * 1024 + (cta >> 5) * 256, 1024);
    stage_tile<2, 512>(reinterpret_cast<float*>(bufb + W3_B),
                       W3 + (size_t)(cta * 2) * 512, 512);
    {
        const int idx = cta * 512 + tid;
        if (idx < 32768)       __stcg(&x1T[idx], __ldcg(b1 + (idx >> 5)));
        else if (idx < 49152)  { int j = idx - 32768; __stcg(&x2T[j], __ldcg(b2 + (j >> 5))); }
    }

    // ---- Phase 0c: histogram (CTAs 0..31), bins live in B_HI region --------------
    if (cta < 32) {
        float* sh = reinterpret_cast<float*>(bufb + B_HI_B);   // 3072 floats
        #pragma unroll
        for (int i = tid; i < 3072; i += 512) sh[i] = 0.0f;
        if (tid < 3) ssum[tid] = 0.0f;
        __syncthreads();

        if (r0 > 0.0f && g0 > 0.0f && l0 > 0.0f) {
            float w  = sqrtf(r0 * r0 + g0 * g0 + l0 * l0);
            float lr = logf(r0), lg = logf(g0), lb = logf(l0);
            hist_add(&sh[0],    lr - lb, lr - lg, w);
            hist_add(&sh[1024], lg - lb, lg - lr, w);
            hist_add(&sh[2048], lb - lg, lb - lr, w);
        }
        if (r1 > 0.0f && g1 > 0.0f && l1 > 0.0f) {
            float w  = sqrtf(r1 * r1 + g1 * g1 + l1 * l1);
            float lr = logf(r1), lg = logf(g1), lb = logf(l1);
            hist_add(&sh[0],    lr - lb, lr - lg, w);
            hist_add(&sh[1024], lg - lb, lg - lr, w);
            hist_add(&sh[2048], lb - lg, lb - lr, w);
        }
        __syncthreads();

        #pragma unroll
        for (int c = 0; c < 3; ++c) {
            float s = sh[c * 1024 + tid] + sh[c * 1024 + tid + 512];
            #pragma unroll
            for (int o = 16; o > 0; o >>= 1) s += __shfl_down_sync(0xffffffffu, s, o);
            if ((tid & 31) == 0) atomicAdd(&ssum[c], s);
        }
        __syncthreads();

        // pair-packed write: histP[(k/2)*64 + b*2 + (k&1)]
        #pragma unroll
        for (int i = tid; i < 1024; i += 512) {
            #pragma unroll
            for (int c = 0; c < 3; ++c) {
                const int k = c * 1024 + i;
                float v = sqrtf(sh[c * 1024 + i] / ssum[c]);
                __stcg(&histP[(k >> 1) * 64 + cta * 2 + (k & 1)], v);
            }
        }
    }

    grid_barrier();

    // =========== fc1: MMA  D[32n x 32b] = W1tile @ histT, K=768 ==================
    {
        // stage B (hist slice) as fp16 hi/lo fragments:
        // u32[((ntile*48 + ks)*32 + t)*2 + u], t=(b&7)*4+(j&3), u=j>>2
        unsigned* bh = reinterpret_cast<unsigned*>(bufb + B_HI_B);
        unsigned* bl = reinterpret_cast<unsigned*>(bufb + B_LO_B);
        #pragma unroll 4
        for (int idx = tid; idx < 12288; idx += 512) {
            const int p = idx >> 5, b = idx & 31;          // p = local k-pair 0..383
            const int gp = (cta >> 5) * 384 + p;
            float2 v = __ldcg(reinterpret_cast<const float2*>(
                histP + (size_t)gp * 64 + b * 2));
            unsigned hi, lo;
            split_h2(v, hi, lo);
            const int ks = p >> 3, j = p & 7, ntile = b >> 3, nn = b & 7;
            const int t = nn * 4 + (j & 3);
            const int b32i = ((ntile * 48 + ks) * 32 + t) * 2 + (j >> 2);
            bh[b32i] = hi;
            bl[b32i] = lo;
        }
        __syncthreads();

        const int tileid = wid & 7, khalf = wid >> 3;
        const int mtile = tileid >> 2, ntile = tileid & 3;
        const uint4* Ah = reinterpret_cast<const uint4*>(bufb + A_HI_B)
                        + ((mtile * 48 + khalf * 24) * 32 + lane);
        const uint4* Al = reinterpret_cast<const uint4*>(bufb + A_LO_B)
                        + ((mtile * 48 + khalf * 24) * 32 + lane);
        const uint2* Bh = reinterpret_cast<const uint2*>(bufb + B_HI_B)
                        + ((ntile * 48 + khalf * 24) * 32 + lane);
        const uint2* Bl = reinterpret_cast<const uint2*>(bufb + B_LO_B)
                        + ((ntile * 48 + khalf * 24) * 32 + lane);

        float d0 = 0.f, d1 = 0.f, d2 = 0.f, d3 = 0.f;
        #pragma unroll
        for (int s = 0; s < 24; ++s) {
            uint4 ah = Ah[s * 32];
            uint4 al = Al[s * 32];
            uint2 vbh = Bh[s * 32];
            uint2 vbl = Bl[s * 32];
            mma16816(d0, d1, d2, d3, ah, vbh);
            mma16816(d0, d1, d2, d3, ah, vbl);
            mma16816(d0, d1, d2, d3, al, vbh);
        }

        const int n_g  = (cta & 31) * 32 + mtile * 16 + (lane >> 2);
        const int bcol = ntile * 8 + (lane & 3) * 2;
        atomicAdd(&x1T[(size_t)n_g * 32 + bcol],           d0);
        atomicAdd(&x1T[(size_t)n_g * 32 + bcol + 1],       d1);
        atomicAdd(&x1T[(size_t)(n_g + 8) * 32 + bcol],     d2);
        atomicAdd(&x1T[(size_t)(n_g + 8) * 32 + bcol + 1], d3);
        __syncthreads();
    }
    grid_barrier();

    // =========== fc2: 512 x 1024 — 32 nb(16 n) x 4 kb(256 K), relu-in ===========
    fc_compute<256, 16, 8, 2, 8, 1, true, false, true>(
        x1T, reinterpret_cast<float*>(bufb + W2_B), nullptr, x2T, 0,
        reinterpret_cast<float*>(bufb + A_HI_B), (cta & 31) * 16, (cta >> 5) * 256);
    grid_barrier();

    // =========== fc3: 256 x 512 — 2 n/CTA, full K, relu-in, direct out ============
    fc_compute<512, 2, 2, 1, 16, 1, true, false, false>(
        x2T, reinterpret_cast<float*>(bufb + W3_B), b3, out, 256,
        reinterpret_cast<float*>(bufb + A_HI_B), cta * 2, 0);
}

extern "C" void kernel_launch(void* const* d_in, const int* in_sizes, int n_in,
                              void* d_out, int out_size) {
    const float* inp = (const float*)d_in[0];
    const float* W1  = (const float*)d_in[1];
    const float* b1  = (const float*)d_in[2];
    const float* W2  = (const float*)d_in[3];
    const float* b2  = (const float*)d_in[4];
    const float* W3  = (const float*)d_in[5];
    const float* b3  = (const float*)d_in[6];
    float* out = (float*)d_out;

    float* histP; cudaGetSymbolAddress((void**)&histP, g_histP);
    float* x1T;   cudaGetSymbolAddress((void**)&x1T,   g_x1T);
    float* x2T;   cudaGetSymbolAddress((void**)&x2T,   g_x2T);

    cudaFuncSetAttribute(fused_kernel,
                         cudaFuncAttributeMaxDynamicSharedMemorySize, SMEM_BYTES);
    fused_kernel<<<NCTA, 512, SMEM_BYTES>>>(inp, W1, b1, W2, b2, W3, b3, out,
                                            histP, x1T, x2T);
}

// round 17
// speedup vs baseline: 1.0826x; 1.0826x over previous
#include <cuda_runtime.h>
#include <math.h>

// ---------------------------------------------------------------------------
// SimplifiedIFEBranch — R17: R7 pipeline, but fc1->fc2->fc3 synchronized by
// fine-grained producer-consumer counters (phase overlap) instead of global
// barriers. ONE grid barrier remains (hist -> fc1). Counters reset in phase 0.
// ---------------------------------------------------------------------------

#define NBINS 32
#define NCTA  128

// dynamic smem layout (floats)
#define W1_OFF 0            // 32 x 768  = 24576 floats (96 KB)
#define W2_OFF 24576        // 16 x 256  =  4096 floats (16 KB)
#define W3_OFF 28672        //  2 x 512  =  1024 floats ( 4 KB)
#define SMEM_FLOATS 29696
#define SMEM_BYTES  (SMEM_FLOATS * 4)

__device__ __forceinline__ float c_LO() { return (float)(-3.2 - (6.4 / 256.0) / 2.0); }
__device__ __forceinline__ float c_HI() { return (float)( 3.2 - (6.4 / 256.0) / 2.0); }
__device__ __forceinline__ float c_BW() {
    return (float)(((3.2 - (6.4 / 256.0) / 2.0) - (-3.2 - (6.4 / 256.0) / 2.0)) / 32.0);
}

// Scratch (__device__ globals; no allocation allowed)
__device__ float g_histP[3072 * 32];   // pair-packed: [(k/2)][b][2]
__device__ float g_x1T[1024 * 32];     // [n][b] accum, bias-preinit
__device__ float g_x2T[512 * 32];
__device__ unsigned int g_bar_count = 0;
__device__ unsigned int g_bar_gen   = 0;
__device__ unsigned int g_done1[32];   // per fc1 nb-block completion (to 4)
__device__ unsigned int g_done2;       // fc2 completion (to 128)

// ---- packed f32x2 helpers ---------------------------------------------------
__device__ __forceinline__ unsigned long long pack2(float x, float y) {
    unsigned long long r;
    asm("mov.b64 %0, {%1, %2};" : "=l"(r) : "f"(x), "f"(y));
    return r;
}
__device__ __forceinline__ void ffma2(unsigned long long& d,
                                      unsigned long long a, unsigned long long b) {
    asm("fma.rn.f32x2 %0, %1, %2, %0;" : "+l"(d) : "l"(a), "l"(b));
}
__device__ __forceinline__ float unpack_sum(unsigned long long p) {
    float lo, hi;
    asm("mov.b64 {%0, %1}, %2;" : "=f"(lo), "=f"(hi) : "l"(p));
    return lo + hi;
}

// ---- software grid barrier (hist -> fc1 only) ----------------------------------
__device__ __forceinline__ void grid_barrier() {
    __syncthreads();
    if (threadIdx.x == 0) {
        unsigned gen = *(volatile unsigned*)&g_bar_gen;
        __threadfence();
        unsigned old = atomicAdd(&g_bar_count, 1u);
        if (old == NCTA - 1) {
            g_bar_count = 0;
            __threadfence();
            atomicAdd(&g_bar_gen, 1u);
        } else {
            while (*(volatile unsigned*)&g_bar_gen == gen) { __nanosleep(32); }
        }
        __threadfence();
    }
    __syncthreads();
}

// ---- histogram helper -----------------------------------------------------------
__device__ __forceinline__ void hist_add(float* h, float Iu, float Iv, float w) {
    const float LO = c_LO(), HI = c_HI(), BW = c_BW();
    if (Iu >= LO && Iu <= HI && Iv >= LO && Iv <= HI) {
        int iu = (int)floorf((Iu - LO) / BW);
        int iv = (int)floorf((Iv - LO) / BW);
        iu = min(max(iu, 0), NBINS - 1);
        iv = min(max(iv, 0), NBINS - 1);
        atomicAdd(&h[iu * NBINS + iv], w);
    }
}

// ---- coalesced W tile stage (global -> smem), each element once ----------------
template <int ROWS, int COLS>
__device__ __forceinline__ void stage_tile(float* dst, const float* src, int ld) {
    constexpr int F4 = ROWS * COLS / 4;
    constexpr int RF = COLS / 4;
    #pragma unroll
    for (int f = threadIdx.x; f < F4; f += 512) {
        const int row = f / RF, col = f - row * RF;
        float4 v = __ldcg(reinterpret_cast<const float4*>(src + (size_t)row * ld + col * 4));
        reinterpret_cast<float4*>(dst)[f] = v;
    }
}

// ---- FC compute (W tile already in smem) — R7-exact -------------------------------
template <int KS, int NROWS, int NT, int NG, int KG, int HALVES,
          bool RELU_IN, bool PACKED_A, bool ATOMIC_OUT>
__device__ __forceinline__ void fc_compute(const float* __restrict__ AT,
                                           const float* wtile,
                                           const float* __restrict__ bias,
                                           float* __restrict__ dest, int ldo,
                                           float* scratch, int n0, int K0) {
    constexpr int CH = KS / KG;
    constexpr int NK = CH / HALVES;
    const int tid  = threadIdx.x;
    const int lane = tid & 31;
    const int w    = tid >> 5;
    const int kg   = w / NG;
    const int ng   = w % NG;

    unsigned long long acc2[NT];
    #pragma unroll
    for (int t = 0; t < NT; ++t) acc2[t] = 0ull;

    const int kbase = K0 + kg * CH;
    const float* wrow0 = wtile + (size_t)(ng * NT) * KS + kg * CH;

    #pragma unroll
    for (int h = 0; h < HALVES; ++h) {
        const int kh = kbase + h * NK;
        unsigned long long ap[NK / 2];
        if (PACKED_A) {
            const unsigned long long* src =
                reinterpret_cast<const unsigned long long*>(AT)
                + (size_t)(kh >> 1) * 32 + lane;
            #pragma unroll
            for (int j = 0; j < NK / 2; ++j) ap[j] = __ldcg(src + (size_t)j * 32);
        } else {
            #pragma unroll
            for (int j = 0; j < NK / 2; ++j) {
                float a0 = __ldcg(AT + (size_t)(kh + 2 * j) * 32 + lane);
                float a1 = __ldcg(AT + (size_t)(kh + 2 * j + 1) * 32 + lane);
                if (RELU_IN) { a0 = fmaxf(a0, 0.f); a1 = fmaxf(a1, 0.f); }
                ap[j] = pack2(a0, a1);
            }
        }
        #pragma unroll
        for (int j2 = 0; j2 < NK / 4; ++j2) {
            #pragma unroll
            for (int t = 0; t < NT; ++t) {
                ulonglong2 wv = *reinterpret_cast<const ulonglong2*>(
                    wrow0 + (size_t)t * KS + h * NK + 4 * j2);
                ffma2(acc2[t], wv.x, ap[2 * j2]);
                ffma2(acc2[t], wv.y, ap[2 * j2 + 1]);
            }
        }
    }
    __syncthreads();                        // wtile reads done; scratch may alias

    #pragma unroll
    for (int t = 0; t < NT; ++t)
        scratch[(w * NT + t) * 32 + lane] = unpack_sum(acc2[t]);
    __syncthreads();

    for (int n = w; n < NROWS; n += 16) {
        const int nng = n / NT, tt = n % NT;
        float s = 0.0f;
        #pragma unroll
        for (int kk = 0; kk < KG; ++kk)
            s += scratch[((kk * NG + nng) * NT + tt) * 32 + lane];
        if (ATOMIC_OUT) {
            atomicAdd(&dest[(size_t)(n0 + n) * 32 + lane], s);
        } else {
            s += __ldcg(bias + n0 + n);
            s = fmaxf(s, 0.0f);
            dest[(size_t)lane * ldo + n0 + n] = s;
        }
    }
    __syncthreads();
}

// ---- the one kernel ----------------------------------------------------------------
__global__ __launch_bounds__(512, 1) void fused_kernel(
    const float* __restrict__ img,
    const float* __restrict__ W1, const float* __restrict__ b1,
    const float* __restrict__ W2, const float* __restrict__ b2,
    const float* __restrict__ W3, const float* __restrict__ b3,
    float* __restrict__ out,
    float* __restrict__ histP, float* __restrict__ x1T, float* __restrict__ x2T) {

    extern __shared__ float buf[];          // W tiles + reduce scratch
    __shared__ float sh[3 * 1024];          // hist bins (static, coexists)
    __shared__ float ssum[3];

    const int cta = blockIdx.x;
    const int tid = threadIdx.x;

    // ---- hist pixel loads first (latency hidden under staging) --------------
    float r0 = 0, g0 = 0, l0 = 0, r1 = 0, g1 = 0, l1 = 0;
    if (cta < 32) {
        const float* base = img + (size_t)cta * 3 * 262144;
        const int p0 = tid, p1 = tid + 512;
        const int off0 = ((p0 >> 5) * 16) * 512 + ((p0 & 31) * 16);
        const int off1 = ((p1 >> 5) * 16) * 512 + ((p1 & 31) * 16);
        r0 = __ldcg(base + off0);
        g0 = __ldcg(base + 262144 + off0);
        l0 = __ldcg(base + 524288 + off0);
        r1 = __ldcg(base + off1);
        g1 = __ldcg(base + 262144 + off1);
        l1 = __ldcg(base + 524288 + off1);
    }

    // ---- stage this CTA's W tiles --------------------------------------------
    stage_tile<32, 768>(buf + W1_OFF,
                        W1 + (size_t)((cta & 31) * 32) * 3072 + (cta >> 5) * 768, 3072);
    stage_tile<16, 256>(buf + W2_OFF,
                        W2 + (size_t)((cta & 31) * 16) * 1024 + (cta >> 5) * 256, 1024);
    stage_tile<2, 512>(buf + W3_OFF, W3 + (size_t)(cta * 2) * 512, 512);

    // ---- bias pre-init + counter reset (ordered by the grid barrier) ---------
    {
        const int idx = cta * 512 + tid;
        if (idx < 32768)       __stcg(&x1T[idx], __ldcg(b1 + (idx >> 5)));
        else if (idx < 49152)  { int j = idx - 32768; __stcg(&x2T[j], __ldcg(b2 + (j >> 5))); }
    }
    if (cta == 127) {
        if (tid < 32) g_done1[tid] = 0;
        if (tid == 32) g_done2 = 0;
    }

    // ---- histogram (CTAs 0..31) ------------------------------------------------
    if (cta < 32) {
        const int b = cta;
        #pragma unroll
        for (int i = tid; i < 3072; i += 512) sh[i] = 0.0f;
        if (tid < 3) ssum[tid] = 0.0f;
        __syncthreads();

        if (r0 > 0.0f && g0 > 0.0f && l0 > 0.0f) {
            float w  = sqrtf(r0 * r0 + g0 * g0 + l0 * l0);
            float lr = logf(r0), lg = logf(g0), lb = logf(l0);
            hist_add(&sh[0],    lr - lb, lr - lg, w);
            hist_add(&sh[1024], lg - lb, lg - lr, w);
            hist_add(&sh[2048], lb - lg, lb - lr, w);
        }
        if (r1 > 0.0f && g1 > 0.0f && l1 > 0.0f) {
            float w  = sqrtf(r1 * r1 + g1 * g1 + l1 * l1);
            float lr = logf(r1), lg = logf(g1), lb = logf(l1);
            hist_add(&sh[0],    lr - lb, lr - lg, w);
            hist_add(&sh[1024], lg - lb, lg - lr, w);
            hist_add(&sh[2048], lb - lg, lb - lr, w);
        }
        __syncthreads();

        #pragma unroll
        for (int c = 0; c < 3; ++c) {
            float s = sh[c * 1024 + tid] + sh[c * 1024 + tid + 512];
            #pragma unroll
            for (int o = 16; o > 0; o >>= 1) s += __shfl_down_sync(0xffffffffu, s, o);
            if ((tid & 31) == 0) atomicAdd(&ssum[c], s);
        }
        __syncthreads();

        // pair-packed write: histP[(k/2)*64 + b*2 + (k&1)]
        #pragma unroll
        for (int i = tid; i < 1024; i += 512) {
            #pragma unroll
            for (int c = 0; c < 3; ++c) {
                const int k = c * 1024 + i;
                float v = sqrtf(sh[c * 1024 + i] / ssum[c]);
                __stcg(&histP[(k >> 1) * 64 + b * 2 + (k & 1)], v);
            }
        }
    }

    grid_barrier();      // hist + bias preinit + counter resets visible

    // =========== fc1: 1024 x 3072 — 32 nb(32 n) x 4 kb(768 K) ==================
    {
        const int nb = cta & 31;
        fc_compute<768, 32, 16, 2, 8, 2, false, true, true>(
            histP, buf + W1_OFF, nullptr, x1T, 0, buf, nb * 32, (cta >> 5) * 768);
        __threadfence();                    // each thread's RED ops visible
        __syncthreads();
        if (tid == 0) atomicAdd(&g_done1[nb], 1u);
    }

    // ---- wait for the 8 fc1 nb-blocks covering this CTA's fc2 K-slice ----------
    {
        const int base_nb = (cta >> 5) * 8;
        if (tid < 8) {
            volatile unsigned* c = &g_done1[base_nb + tid];
            while (*c < 4u) {}
        }
        __threadfence();
        __syncthreads();
    }

    // =========== fc2: 512 x 1024 — 32 nb(16 n) x 4 kb(256 K), relu-in ==========
    fc_compute<256, 16, 8, 2, 8, 1, true, false, true>(
        x1T, buf + W2_OFF, nullptr, x2T, 0, buf, (cta & 31) * 16, (cta >> 5) * 256);
    __threadfence();
    __syncthreads();
    if (tid == 0) atomicAdd(&g_done2, 1u);

    // ---- wait for ALL fc2 partials (fc3 uses full K=512) ------------------------
    {
        if (tid == 0) {
            volatile unsigned* c = &g_done2;
            while (*c < 128u) {}
        }
        __threadfence();
        __syncthreads();
    }

    // =========== fc3: 256 x 512 — 2 neurons/CTA, full K, relu-in, direct out ====
    fc_compute<512, 2, 2, 1, 16, 1, true, false, false>(
        x2T, buf + W3_OFF, b3, out, 256, buf, cta * 2, 0);
}

extern "C" void kernel_launch(void* const* d_in, const int* in_sizes, int n_in,
                              void* d_out, int out_size) {
    const float* inp = (const float*)d_in[0];
    const float* W1  = (const float*)d_in[1];
    const float* b1  = (const float*)d_in[2];
    const float* W2  = (const float*)d_in[3];
    const float* b2  = (const float*)d_in[4];
    const float* W3  = (const float*)d_in[5];
    const float* b3  = (const float*)d_in[6];
    float* out = (float*)d_out;

    float* histP; cudaGetSymbolAddress((void**)&histP, g_histP);
    float* x1T;   cudaGetSymbolAddress((void**)&x1T,   g_x1T);
    float* x2T;   cudaGetSymbolAddress((void**)&x2T,   g_x2T);

    cudaFuncSetAttribute(fused_kernel,
                         cudaFuncAttributeMaxDynamicSharedMemorySize, SMEM_BYTES);
    fused_kernel<<<NCTA, 512, SMEM_BYTES>>>(inp, W1, b1, W2, b2, W3, b3, out,
                                            histP, x1T, x2T);
}